// round 2
// baseline (speedup 1.0000x reference)
#include <cuda_runtime.h>
#include <cuda_bf16.h>
#include <cstdint>

// ---------------------------------------------------------------------------
// total = -(1/L) * sum_i dot(q_hat_i, q_real_i)
//       + sum_{i,j} max(0, <pred_i, gt_j> - <pred_i, gt_i> + 1)
// L=8192, B=4096, D=1024.
// GEMM pred @ gt^T in bf16 via mma.sync.m16n8k16 (sm_103 target has no
// tcgen05 — ptxas rejects 'a'-suffix features), hinge fused in registers.
// ---------------------------------------------------------------------------

#define L_DIM 8192
#define B_DIM 4096
#define D_DIM 1024

__device__ double g_glob;
__device__ double g_local;
__device__ float g_pos[B_DIM];
__device__ __nv_bfloat16 g_predb[(size_t)B_DIM * D_DIM];
__device__ __nv_bfloat16 g_gtb[(size_t)B_DIM * D_DIM];

// ---------------------------------------------------------------------------
__device__ __forceinline__ uint32_t smem_u32(const void* p) {
    uint32_t a;
    asm("{ .reg .u64 t; cvta.to.shared.u64 t, %1; cvt.u32.u64 %0, t; }"
        : "=r"(a) : "l"(p));
    return a;
}

__device__ __forceinline__ void cp_async16(uint32_t smem, const void* gmem) {
    asm volatile("cp.async.cg.shared.global [%0], [%1], 16;"
                 :: "r"(smem), "l"(gmem) : "memory");
}
#define CP_COMMIT() asm volatile("cp.async.commit_group;" ::: "memory")
#define CP_WAIT2()  asm volatile("cp.async.wait_group 2;" ::: "memory")

#define LDSM_X4(r0, r1, r2, r3, addr) \
    asm volatile("ldmatrix.sync.aligned.m8n8.x4.shared.b16 {%0,%1,%2,%3}, [%4];" \
                 : "=r"(r0), "=r"(r1), "=r"(r2), "=r"(r3) : "r"(addr))

__device__ __forceinline__ void mma16816(float* c, const uint32_t* a,
                                         uint32_t b0, uint32_t b1) {
    asm volatile(
        "mma.sync.aligned.m16n8k16.row.col.f32.bf16.bf16.f32 "
        "{%0,%1,%2,%3}, {%4,%5,%6,%7}, {%8,%9}, {%0,%1,%2,%3};"
        : "+f"(c[0]), "+f"(c[1]), "+f"(c[2]), "+f"(c[3])
        : "r"(a[0]), "r"(a[1]), "r"(a[2]), "r"(a[3]), "r"(b0), "r"(b1));
}

// ---------------------------------------------------------------------------
// Kernel 0: zero accumulators (graph-replay safe)
// ---------------------------------------------------------------------------
__global__ void zero_kernel() {
    g_glob = 0.0;
    g_local = 0.0;
}

// ---------------------------------------------------------------------------
// Kernel 1: fp32 -> bf16 convert for pred/gt + pos[i] = dot(pred_i, gt_i)
// grid = B_DIM blocks x 256 threads; one float4 per thread (D=1024)
// ---------------------------------------------------------------------------
__global__ void prep_kernel(const float* __restrict__ pred,
                            const float* __restrict__ gt) {
    const int r = blockIdx.x;
    const int t = threadIdx.x;
    const float4 pv = ((const float4*)(pred + (size_t)r * D_DIM))[t];
    const float4 gv = ((const float4*)(gt + (size_t)r * D_DIM))[t];

    float acc = pv.x * gv.x + pv.y * gv.y + pv.z * gv.z + pv.w * gv.w;

    __nv_bfloat162 pa = __floats2bfloat162_rn(pv.x, pv.y);
    __nv_bfloat162 pb = __floats2bfloat162_rn(pv.z, pv.w);
    __nv_bfloat162 ga = __floats2bfloat162_rn(gv.x, gv.y);
    __nv_bfloat162 gb = __floats2bfloat162_rn(gv.z, gv.w);
    uint2 pw, gw;
    pw.x = *reinterpret_cast<uint32_t*>(&pa);
    pw.y = *reinterpret_cast<uint32_t*>(&pb);
    gw.x = *reinterpret_cast<uint32_t*>(&ga);
    gw.y = *reinterpret_cast<uint32_t*>(&gb);
    ((uint2*)(g_predb + (size_t)r * D_DIM))[t] = pw;
    ((uint2*)(g_gtb + (size_t)r * D_DIM))[t] = gw;

    #pragma unroll
    for (int o = 16; o > 0; o >>= 1)
        acc += __shfl_xor_sync(0xFFFFFFFFu, acc, o);
    __shared__ float ws[8];
    if ((t & 31) == 0) ws[t >> 5] = acc;
    __syncthreads();
    if (t == 0) {
        float s = 0.f;
        #pragma unroll
        for (int w = 0; w < 8; w++) s += ws[w];
        g_pos[r] = s;
    }
}

// ---------------------------------------------------------------------------
// Kernel 2: local loss partial:  g_local += sum(q_hat * q_real)
// ---------------------------------------------------------------------------
__global__ void local_kernel(const float* __restrict__ a,
                             const float* __restrict__ b) {
    const size_t n4 = (size_t)L_DIM * D_DIM / 4;
    float acc = 0.f;
    for (size_t i = (size_t)blockIdx.x * blockDim.x + threadIdx.x; i < n4;
         i += (size_t)gridDim.x * blockDim.x) {
        float4 av = ((const float4*)a)[i];
        float4 bv = ((const float4*)b)[i];
        acc += av.x * bv.x + av.y * bv.y + av.z * bv.z + av.w * bv.w;
    }
    #pragma unroll
    for (int o = 16; o > 0; o >>= 1)
        acc += __shfl_xor_sync(0xFFFFFFFFu, acc, o);
    __shared__ float ws[8];
    const int t = threadIdx.x;
    if ((t & 31) == 0) ws[t >> 5] = acc;
    __syncthreads();
    if (t == 0) {
        float s = 0.f;
        #pragma unroll
        for (int w = 0; w < 8; w++) s += ws[w];
        atomicAdd(&g_local, (double)s);
    }
}

// ---------------------------------------------------------------------------
// Kernel 3: bf16 GEMM 128x128 tile via mma.sync + fused hinge epilogue.
// grid = (32, 32), 256 threads (8 warps: 2(m) x 4(n), warp tile 64x32).
// 4-stage cp.async pipeline, BK=64 (128 B per row), XOR-swizzled smem.
// Stage layout: A @ st*32768 (16 KB), B @ st*32768+16384 (16 KB).
// ---------------------------------------------------------------------------
static constexpr int GEMM_SMEM_DYN = 4 * 32768;  // 128 KB

__global__ void __launch_bounds__(256, 1) gemm_hinge_kernel() {
    extern __shared__ char smem_raw[];
    const uint32_t sb = smem_u32(smem_raw);
    const int tid = threadIdx.x;
    const int wid = tid >> 5;
    const int lane = tid & 31;
    const int warp_m = wid >> 2;   // 0..1
    const int warp_n = wid & 3;    // 0..3

    const __nv_bfloat16* __restrict__ Ab = g_predb + (size_t)blockIdx.y * 128 * D_DIM;
    const __nv_bfloat16* __restrict__ Bb = g_gtb + (size_t)blockIdx.x * 128 * D_DIM;

    float acc[4][4][4];
    #pragma unroll
    for (int i = 0; i < 4; i++)
        #pragma unroll
        for (int j = 0; j < 4; j++)
            #pragma unroll
            for (int e = 0; e < 4; e++) acc[i][j][e] = 0.f;

    // Loads one K-chunk (64 cols) of A and B tiles into stage st.
    auto load_stage = [&](int kc, int st) {
        const uint32_t baseA = sb + st * 32768;
        const uint32_t baseB = baseA + 16384;
        #pragma unroll
        for (int i = 0; i < 4; i++) {
            const int idx = tid + i * 256;      // 0..1023
            const int row = idx >> 3;           // 0..127
            const int c = idx & 7;              // 16B chunk within 128B row
            const uint32_t soff = row * 128 + ((c ^ (row & 7)) << 4);
            cp_async16(baseA + soff, Ab + (size_t)row * D_DIM + kc * 64 + c * 8);
            cp_async16(baseB + soff, Bb + (size_t)row * D_DIM + kc * 64 + c * 8);
        }
    };

    load_stage(0, 0); CP_COMMIT();
    load_stage(1, 1); CP_COMMIT();
    load_stage(2, 2); CP_COMMIT();

    #pragma unroll 1
    for (int kc = 0; kc < 16; ++kc) {
        CP_WAIT2();
        __syncthreads();
        if (kc + 3 < 16) load_stage(kc + 3, (kc + 3) & 3);
        CP_COMMIT();  // commit every iter (possibly empty) to keep count uniform

        const uint32_t baseA = sb + (kc & 3) * 32768;
        const uint32_t baseB = baseA + 16384;

        #pragma unroll
        for (int ks = 0; ks < 4; ks++) {   // four k16 steps per 64-wide chunk
            uint32_t a[4][4], b[2][4];
            #pragma unroll
            for (int mt = 0; mt < 4; mt++) {
                const int row = warp_m * 64 + mt * 16 + (lane & 15);
                const int chunk = ks * 2 + (lane >> 4);
                LDSM_X4(a[mt][0], a[mt][1], a[mt][2], a[mt][3],
                        baseA + row * 128 + ((chunk ^ (row & 7)) << 4));
            }
            #pragma unroll
            for (int nt = 0; nt < 2; nt++) {
                const int row = warp_n * 32 + nt * 16 + (lane & 15);
                const int chunk = ks * 2 + (lane >> 4);
                LDSM_X4(b[nt][0], b[nt][1], b[nt][2], b[nt][3],
                        baseB + row * 128 + ((chunk ^ (row & 7)) << 4));
            }
            #pragma unroll
            for (int mt = 0; mt < 4; mt++)
                #pragma unroll
                for (int nt = 0; nt < 4; nt++)
                    mma16816(acc[mt][nt], a[mt],
                             b[nt >> 1][nt & 1], b[nt >> 1][(nt & 1) + 2]);
        }
    }

    // ---- fused hinge epilogue: acc already in registers ----
    float partial = 0.f;
    #pragma unroll
    for (int mt = 0; mt < 4; mt++) {
        const int r0 = blockIdx.y * 128 + warp_m * 64 + mt * 16 + (lane >> 2);
        const float p0 = __ldg(&g_pos[r0]) - 1.0f;      // v - pos + 1 = v - (pos-1)
        const float p1 = __ldg(&g_pos[r0 + 8]) - 1.0f;
        #pragma unroll
        for (int nt = 0; nt < 4; nt++) {
            partial += fmaxf(acc[mt][nt][0] - p0, 0.f);
            partial += fmaxf(acc[mt][nt][1] - p0, 0.f);
            partial += fmaxf(acc[mt][nt][2] - p1, 0.f);
            partial += fmaxf(acc[mt][nt][3] - p1, 0.f);
        }
    }

    #pragma unroll
    for (int o = 16; o > 0; o >>= 1)
        partial += __shfl_xor_sync(0xFFFFFFFFu, partial, o);
    __shared__ float warpsum[8];
    if (lane == 0) warpsum[wid] = partial;
    __syncthreads();
    if (tid == 0) {
        float s = 0.f;
        #pragma unroll
        for (int w = 0; w < 8; w++) s += warpsum[w];
        atomicAdd(&g_glob, (double)s);
    }
}

// ---------------------------------------------------------------------------
__global__ void finalize_kernel(float* out) {
    out[0] = (float)(g_glob - g_local / (double)L_DIM);
}

// ---------------------------------------------------------------------------
extern "C" void kernel_launch(void* const* d_in, const int* in_sizes, int n_in,
                              void* d_out, int out_size) {
    const float* q_hat  = (const float*)d_in[0];
    const float* q_real = (const float*)d_in[1];
    const float* gt     = (const float*)d_in[2];
    const float* pred   = (const float*)d_in[3];

    (void)in_sizes; (void)n_in; (void)out_size;

    zero_kernel<<<1, 1>>>();
    prep_kernel<<<B_DIM, 256>>>(pred, gt);
    local_kernel<<<1024, 256>>>(q_hat, q_real);

    static bool attr_set = false;
    if (!attr_set) {
        cudaFuncSetAttribute(gemm_hinge_kernel,
                             cudaFuncAttributeMaxDynamicSharedMemorySize,
                             GEMM_SMEM_DYN);
        attr_set = true;
    }
    gemm_hinge_kernel<<<dim3(32, 32), 256, GEMM_SMEM_DYN>>>();

    finalize_kernel<<<1, 1>>>((float*)d_out);
}

// round 3
// speedup vs baseline: 1.1401x; 1.1401x over previous
#include <cuda_runtime.h>
#include <cuda_bf16.h>
#include <cstdint>

// ---------------------------------------------------------------------------
// total = -(1/L) * sum_i dot(q_hat_i, q_real_i)
//       + sum_{i,j} max(0, <pred_i, gt_j> - <pred_i, gt_i> + 1)
// L=8192, B=4096, D=1024.
// GEMM pred @ gt^T in bf16 via mma.sync.m16n8k16, hinge fused in registers.
// R3: 3-stage pipeline (96 KB smem) so 2 CTAs co-reside per SM.
// ---------------------------------------------------------------------------

#define L_DIM 8192
#define B_DIM 4096
#define D_DIM 1024

__device__ double g_glob;
__device__ double g_local;
__device__ float g_pos[B_DIM];
__device__ __nv_bfloat16 g_predb[(size_t)B_DIM * D_DIM];
__device__ __nv_bfloat16 g_gtb[(size_t)B_DIM * D_DIM];

// ---------------------------------------------------------------------------
__device__ __forceinline__ uint32_t smem_u32(const void* p) {
    uint32_t a;
    asm("{ .reg .u64 t; cvta.to.shared.u64 t, %1; cvt.u32.u64 %0, t; }"
        : "=r"(a) : "l"(p));
    return a;
}

__device__ __forceinline__ void cp_async16(uint32_t smem, const void* gmem) {
    asm volatile("cp.async.cg.shared.global [%0], [%1], 16;"
                 :: "r"(smem), "l"(gmem) : "memory");
}
#define CP_COMMIT() asm volatile("cp.async.commit_group;" ::: "memory")
#define CP_WAIT1()  asm volatile("cp.async.wait_group 1;" ::: "memory")

#define LDSM_X4(r0, r1, r2, r3, addr) \
    asm volatile("ldmatrix.sync.aligned.m8n8.x4.shared.b16 {%0,%1,%2,%3}, [%4];" \
                 : "=r"(r0), "=r"(r1), "=r"(r2), "=r"(r3) : "r"(addr))

__device__ __forceinline__ void mma16816(float* c, const uint32_t* a,
                                         uint32_t b0, uint32_t b1) {
    asm volatile(
        "mma.sync.aligned.m16n8k16.row.col.f32.bf16.bf16.f32 "
        "{%0,%1,%2,%3}, {%4,%5,%6,%7}, {%8,%9}, {%0,%1,%2,%3};"
        : "+f"(c[0]), "+f"(c[1]), "+f"(c[2]), "+f"(c[3])
        : "r"(a[0]), "r"(a[1]), "r"(a[2]), "r"(a[3]), "r"(b0), "r"(b1));
}

// ---------------------------------------------------------------------------
// Kernel 0: zero accumulators (graph-replay safe)
// ---------------------------------------------------------------------------
__global__ void zero_kernel() {
    g_glob = 0.0;
    g_local = 0.0;
}

// ---------------------------------------------------------------------------
// Kernel 1: fp32 -> bf16 convert for pred/gt + pos[i] = dot(pred_i, gt_i)
// ---------------------------------------------------------------------------
__global__ void prep_kernel(const float* __restrict__ pred,
                            const float* __restrict__ gt) {
    const int r = blockIdx.x;
    const int t = threadIdx.x;
    const float4 pv = ((const float4*)(pred + (size_t)r * D_DIM))[t];
    const float4 gv = ((const float4*)(gt + (size_t)r * D_DIM))[t];

    float acc = pv.x * gv.x + pv.y * gv.y + pv.z * gv.z + pv.w * gv.w;

    __nv_bfloat162 pa = __floats2bfloat162_rn(pv.x, pv.y);
    __nv_bfloat162 pb = __floats2bfloat162_rn(pv.z, pv.w);
    __nv_bfloat162 ga = __floats2bfloat162_rn(gv.x, gv.y);
    __nv_bfloat162 gb = __floats2bfloat162_rn(gv.z, gv.w);
    uint2 pw, gw;
    pw.x = *reinterpret_cast<uint32_t*>(&pa);
    pw.y = *reinterpret_cast<uint32_t*>(&pb);
    gw.x = *reinterpret_cast<uint32_t*>(&ga);
    gw.y = *reinterpret_cast<uint32_t*>(&gb);
    ((uint2*)(g_predb + (size_t)r * D_DIM))[t] = pw;
    ((uint2*)(g_gtb + (size_t)r * D_DIM))[t] = gw;

    #pragma unroll
    for (int o = 16; o > 0; o >>= 1)
        acc += __shfl_xor_sync(0xFFFFFFFFu, acc, o);
    __shared__ float ws[8];
    if ((t & 31) == 0) ws[t >> 5] = acc;
    __syncthreads();
    if (t == 0) {
        float s = 0.f;
        #pragma unroll
        for (int w = 0; w < 8; w++) s += ws[w];
        g_pos[r] = s;
    }
}

// ---------------------------------------------------------------------------
// Kernel 2: local loss partial:  g_local += sum(q_hat * q_real)
// ---------------------------------------------------------------------------
__global__ void local_kernel(const float* __restrict__ a,
                             const float* __restrict__ b) {
    const size_t n4 = (size_t)L_DIM * D_DIM / 4;
    float acc = 0.f;
    for (size_t i = (size_t)blockIdx.x * blockDim.x + threadIdx.x; i < n4;
         i += (size_t)gridDim.x * blockDim.x) {
        float4 av = ((const float4*)a)[i];
        float4 bv = ((const float4*)b)[i];
        acc += av.x * bv.x + av.y * bv.y + av.z * bv.z + av.w * bv.w;
    }
    #pragma unroll
    for (int o = 16; o > 0; o >>= 1)
        acc += __shfl_xor_sync(0xFFFFFFFFu, acc, o);
    __shared__ float ws[8];
    const int t = threadIdx.x;
    if ((t & 31) == 0) ws[t >> 5] = acc;
    __syncthreads();
    if (t == 0) {
        float s = 0.f;
        #pragma unroll
        for (int w = 0; w < 8; w++) s += ws[w];
        atomicAdd(&g_local, (double)s);
    }
}

// ---------------------------------------------------------------------------
// Kernel 3: bf16 GEMM 128x128 tile via mma.sync + fused hinge epilogue.
// grid = (32, 32), 256 threads (8 warps: 2(m) x 4(n), warp tile 64x32).
// 3-stage cp.async pipeline (96 KB) -> 2 CTAs per SM.
// Stage layout: A @ st*32768 (16 KB), B @ st*32768+16384 (16 KB).
// ---------------------------------------------------------------------------
static constexpr int GEMM_SMEM_DYN = 3 * 32768;  // 96 KB

__global__ void __launch_bounds__(256, 2) gemm_hinge_kernel() {
    extern __shared__ char smem_raw[];
    const uint32_t sb = smem_u32(smem_raw);
    const int tid = threadIdx.x;
    const int wid = tid >> 5;
    const int lane = tid & 31;
    const int warp_m = wid >> 2;   // 0..1
    const int warp_n = wid & 3;    // 0..3

    const __nv_bfloat16* __restrict__ Ab = g_predb + (size_t)blockIdx.y * 128 * D_DIM;
    const __nv_bfloat16* __restrict__ Bb = g_gtb + (size_t)blockIdx.x * 128 * D_DIM;

    float acc[4][4][4];
    #pragma unroll
    for (int i = 0; i < 4; i++)
        #pragma unroll
        for (int j = 0; j < 4; j++)
            #pragma unroll
            for (int e = 0; e < 4; e++) acc[i][j][e] = 0.f;

    // Loads one K-chunk (64 cols) of A and B tiles into stage st.
    auto load_stage = [&](int kc, int st) {
        const uint32_t baseA = sb + st * 32768;
        const uint32_t baseB = baseA + 16384;
        #pragma unroll
        for (int i = 0; i < 4; i++) {
            const int idx = tid + i * 256;      // 0..1023
            const int row = idx >> 3;           // 0..127
            const int c = idx & 7;              // 16B chunk within 128B row
            const uint32_t soff = row * 128 + ((c ^ (row & 7)) << 4);
            cp_async16(baseA + soff, Ab + (size_t)row * D_DIM + kc * 64 + c * 8);
            cp_async16(baseB + soff, Bb + (size_t)row * D_DIM + kc * 64 + c * 8);
        }
    };

    load_stage(0, 0); CP_COMMIT();
    load_stage(1, 1); CP_COMMIT();

    #pragma unroll 1
    for (int kc = 0; kc < 16; ++kc) {
        CP_WAIT1();          // stage kc resident
        __syncthreads();     // all warps past compute of kc-1 (whose stage we refill)
        if (kc + 2 < 16) load_stage(kc + 2, (kc + 2) % 3);
        CP_COMMIT();         // uniform group count even when empty

        const uint32_t baseA = sb + (kc % 3) * 32768;
        const uint32_t baseB = baseA + 16384;

        #pragma unroll
        for (int ks = 0; ks < 4; ks++) {   // four k16 steps per 64-wide chunk
            uint32_t a[4][4], b[2][4];
            #pragma unroll
            for (int mt = 0; mt < 4; mt++) {
                const int row = warp_m * 64 + mt * 16 + (lane & 15);
                const int chunk = ks * 2 + (lane >> 4);
                LDSM_X4(a[mt][0], a[mt][1], a[mt][2], a[mt][3],
                        baseA + row * 128 + ((chunk ^ (row & 7)) << 4));
            }
            #pragma unroll
            for (int nt = 0; nt < 2; nt++) {
                const int row = warp_n * 32 + nt * 16 + (lane & 15);
                const int chunk = ks * 2 + (lane >> 4);
                LDSM_X4(b[nt][0], b[nt][1], b[nt][2], b[nt][3],
                        baseB + row * 128 + ((chunk ^ (row & 7)) << 4));
            }
            #pragma unroll
            for (int mt = 0; mt < 4; mt++)
                #pragma unroll
                for (int nt = 0; nt < 4; nt++)
                    mma16816(acc[mt][nt], a[mt],
                             b[nt >> 1][nt & 1], b[nt >> 1][(nt & 1) + 2]);
        }
    }

    // ---- fused hinge epilogue: acc already in registers ----
    float partial = 0.f;
    #pragma unroll
    for (int mt = 0; mt < 4; mt++) {
        const int r0 = blockIdx.y * 128 + warp_m * 64 + mt * 16 + (lane >> 2);
        const float p0 = __ldg(&g_pos[r0]) - 1.0f;      // v - pos + 1 = v - (pos-1)
        const float p1 = __ldg(&g_pos[r0 + 8]) - 1.0f;
        #pragma unroll
        for (int nt = 0; nt < 4; nt++) {
            partial += fmaxf(acc[mt][nt][0] - p0, 0.f);
            partial += fmaxf(acc[mt][nt][1] - p0, 0.f);
            partial += fmaxf(acc[mt][nt][2] - p1, 0.f);
            partial += fmaxf(acc[mt][nt][3] - p1, 0.f);
        }
    }

    #pragma unroll
    for (int o = 16; o > 0; o >>= 1)
        partial += __shfl_xor_sync(0xFFFFFFFFu, partial, o);
    __shared__ float warpsum[8];
    if (lane == 0) warpsum[wid] = partial;
    __syncthreads();
    if (tid == 0) {
        float s = 0.f;
        #pragma unroll
        for (int w = 0; w < 8; w++) s += warpsum[w];
        atomicAdd(&g_glob, (double)s);
    }
}

// ---------------------------------------------------------------------------
__global__ void finalize_kernel(float* out) {
    out[0] = (float)(g_glob - g_local / (double)L_DIM);
}

// ---------------------------------------------------------------------------
extern "C" void kernel_launch(void* const* d_in, const int* in_sizes, int n_in,
                              void* d_out, int out_size) {
    const float* q_hat  = (const float*)d_in[0];
    const float* q_real = (const float*)d_in[1];
    const float* gt     = (const float*)d_in[2];
    const float* pred   = (const float*)d_in[3];

    (void)in_sizes; (void)n_in; (void)out_size;

    zero_kernel<<<1, 1>>>();
    prep_kernel<<<B_DIM, 256>>>(pred, gt);
    local_kernel<<<1024, 256>>>(q_hat, q_real);

    static bool attr_set = false;
    if (!attr_set) {
        cudaFuncSetAttribute(gemm_hinge_kernel,
                             cudaFuncAttributeMaxDynamicSharedMemorySize,
                             GEMM_SMEM_DYN);
        attr_set = true;
    }
    gemm_hinge_kernel<<<dim3(32, 32), 256, GEMM_SMEM_DYN>>>();

    finalize_kernel<<<1, 1>>>((float*)d_out);
}

// round 4
// speedup vs baseline: 1.2529x; 1.0989x over previous
#include <cuda_runtime.h>
#include <cuda_bf16.h>
#include <cstdint>

// ---------------------------------------------------------------------------
// total = -(1/L) * sum_i dot(q_hat_i, q_real_i)
//       + sum_{i,j} max(0, <pred_i, gt_j> - <pred_i, gt_i> + 1)
// L=8192, B=4096, D=1024.
// R4: GEMM pred @ gt^T in FP8 (e4m3) via mma.sync.m16n8k32 — halves MMA
// count, LDS traffic, cp.async bytes and barrier count vs bf16. Hinge fused
// in registers. 3-stage cp.async pipeline, 2 CTAs/SM.
// ---------------------------------------------------------------------------

#define L_DIM 8192
#define B_DIM 4096
#define D_DIM 1024

__device__ double g_glob;
__device__ double g_local;
__device__ float g_pos[B_DIM];
// FP8 operand buffers (4 MB each), stored as uint32 (4 e4m3 per word)
__device__ uint32_t g_predq[(size_t)B_DIM * D_DIM / 4];
__device__ uint32_t g_gtq[(size_t)B_DIM * D_DIM / 4];

// ---------------------------------------------------------------------------
__device__ __forceinline__ uint32_t smem_u32(const void* p) {
    uint32_t a;
    asm("{ .reg .u64 t; cvta.to.shared.u64 t, %1; cvt.u32.u64 %0, t; }"
        : "=r"(a) : "l"(p));
    return a;
}

__device__ __forceinline__ void cp_async16(uint32_t smem, const void* gmem) {
    asm volatile("cp.async.cg.shared.global [%0], [%1], 16;"
                 :: "r"(smem), "l"(gmem) : "memory");
}
#define CP_COMMIT() asm volatile("cp.async.commit_group;" ::: "memory")
#define CP_WAIT1()  asm volatile("cp.async.wait_group 1;" ::: "memory")

#define LDSM_X4(r0, r1, r2, r3, addr) \
    asm volatile("ldmatrix.sync.aligned.m8n8.x4.shared.b16 {%0,%1,%2,%3}, [%4];" \
                 : "=r"(r0), "=r"(r1), "=r"(r2), "=r"(r3) : "r"(addr))

// FP8 e4m3 MMA, k32. Fragment layout identical to m16n8k16.b16 with each
// b16 element replaced by a pair of consecutive-k fp8 bytes.
__device__ __forceinline__ void mma16832(float* c, const uint32_t* a,
                                         uint32_t b0, uint32_t b1) {
    asm volatile(
        "mma.sync.aligned.m16n8k32.row.col.f32.e4m3.e4m3.f32 "
        "{%0,%1,%2,%3}, {%4,%5,%6,%7}, {%8,%9}, {%0,%1,%2,%3};"
        : "+f"(c[0]), "+f"(c[1]), "+f"(c[2]), "+f"(c[3])
        : "r"(a[0]), "r"(a[1]), "r"(a[2]), "r"(a[3]), "r"(b0), "r"(b1));
}

__device__ __forceinline__ uint32_t pack_e4m3x4(float4 v) {
    uint16_t lo, hi;
    // cvt packs operand A into the upper byte, B into the lower byte.
    asm("cvt.rn.satfinite.e4m3x2.f32 %0, %1, %2;" : "=h"(lo) : "f"(v.y), "f"(v.x));
    asm("cvt.rn.satfinite.e4m3x2.f32 %0, %1, %2;" : "=h"(hi) : "f"(v.w), "f"(v.z));
    return (uint32_t)lo | ((uint32_t)hi << 16);
}

// ---------------------------------------------------------------------------
// Kernel 1: fp32 -> e4m3 convert for pred/gt + pos[i] = dot(pred_i, gt_i)
// grid = B_DIM x 256 threads; one float4 per thread. Block 0 also zeroes the
// accumulators (no other kernel touches them until prep completes).
// ---------------------------------------------------------------------------
__global__ void prep_kernel(const float* __restrict__ pred,
                            const float* __restrict__ gt) {
    const int r = blockIdx.x;
    const int t = threadIdx.x;
    if (r == 0 && t == 0) {
        g_glob = 0.0;
        g_local = 0.0;
    }
    const float4 pv = ((const float4*)(pred + (size_t)r * D_DIM))[t];
    const float4 gv = ((const float4*)(gt + (size_t)r * D_DIM))[t];

    float acc = pv.x * gv.x + pv.y * gv.y + pv.z * gv.z + pv.w * gv.w;

    g_predq[(size_t)r * (D_DIM / 4) + t] = pack_e4m3x4(pv);
    g_gtq[(size_t)r * (D_DIM / 4) + t] = pack_e4m3x4(gv);

    #pragma unroll
    for (int o = 16; o > 0; o >>= 1)
        acc += __shfl_xor_sync(0xFFFFFFFFu, acc, o);
    __shared__ float ws[8];
    if ((t & 31) == 0) ws[t >> 5] = acc;
    __syncthreads();
    if (t == 0) {
        float s = 0.f;
        #pragma unroll
        for (int w = 0; w < 8; w++) s += ws[w];
        g_pos[r] = s;
    }
}

// ---------------------------------------------------------------------------
// Kernel 2: local loss partial:  g_local += sum(q_hat * q_real)
// ---------------------------------------------------------------------------
__global__ void local_kernel(const float* __restrict__ a,
                             const float* __restrict__ b) {
    const size_t n4 = (size_t)L_DIM * D_DIM / 4;
    float acc = 0.f;
    for (size_t i = (size_t)blockIdx.x * blockDim.x + threadIdx.x; i < n4;
         i += (size_t)gridDim.x * blockDim.x) {
        float4 av = ((const float4*)a)[i];
        float4 bv = ((const float4*)b)[i];
        acc += av.x * bv.x + av.y * bv.y + av.z * bv.z + av.w * bv.w;
    }
    #pragma unroll
    for (int o = 16; o > 0; o >>= 1)
        acc += __shfl_xor_sync(0xFFFFFFFFu, acc, o);
    __shared__ float ws[8];
    const int t = threadIdx.x;
    if ((t & 31) == 0) ws[t >> 5] = acc;
    __syncthreads();
    if (t == 0) {
        float s = 0.f;
        #pragma unroll
        for (int w = 0; w < 8; w++) s += ws[w];
        atomicAdd(&g_local, (double)s);
    }
}

// ---------------------------------------------------------------------------
// Kernel 3: FP8 GEMM 128x128 tile via mma.sync.m16n8k32 + fused hinge.
// grid = (32, 32), 256 threads (8 warps: 2(m) x 4(n), warp tile 64x32).
// BK = 128 fp8 elements = 128 B/row -> 16 KB per operand stage, 3 stages.
// 8 K-chunks. Same XOR swizzle (8 x 16B chunks per 128 B row).
// ---------------------------------------------------------------------------
static constexpr int GEMM_SMEM_DYN = 3 * 32768;  // 96 KB -> 2 CTAs/SM

__global__ void __launch_bounds__(256, 2) gemm_hinge_kernel() {
    extern __shared__ char smem_raw[];
    const uint32_t sb = smem_u32(smem_raw);
    const int tid = threadIdx.x;
    const int wid = tid >> 5;
    const int lane = tid & 31;
    const int warp_m = wid >> 2;   // 0..1
    const int warp_n = wid & 3;    // 0..3

    const uint8_t* __restrict__ Ab =
        (const uint8_t*)g_predq + (size_t)blockIdx.y * 128 * D_DIM;
    const uint8_t* __restrict__ Bb =
        (const uint8_t*)g_gtq + (size_t)blockIdx.x * 128 * D_DIM;

    float acc[4][4][4];
    #pragma unroll
    for (int i = 0; i < 4; i++)
        #pragma unroll
        for (int j = 0; j < 4; j++)
            #pragma unroll
            for (int e = 0; e < 4; e++) acc[i][j][e] = 0.f;

    // Load one K-chunk (128 fp8 = 128 B per row) of A and B into stage st.
    auto load_stage = [&](int kc, int st) {
        const uint32_t baseA = sb + st * 32768;
        const uint32_t baseB = baseA + 16384;
        #pragma unroll
        for (int i = 0; i < 4; i++) {
            const int idx = tid + i * 256;      // 0..1023
            const int row = idx >> 3;           // 0..127
            const int c = idx & 7;              // 16B chunk within 128B row
            const uint32_t soff = row * 128 + ((c ^ (row & 7)) << 4);
            cp_async16(baseA + soff, Ab + (size_t)row * D_DIM + kc * 128 + c * 16);
            cp_async16(baseB + soff, Bb + (size_t)row * D_DIM + kc * 128 + c * 16);
        }
    };

    load_stage(0, 0); CP_COMMIT();
    load_stage(1, 1); CP_COMMIT();

    #pragma unroll 1
    for (int kc = 0; kc < 8; ++kc) {
        CP_WAIT1();          // stage kc resident
        __syncthreads();     // all warps done with the stage we refill
        if (kc + 2 < 8) load_stage(kc + 2, (kc + 2) % 3);
        CP_COMMIT();         // uniform group count even when empty

        const uint32_t baseA = sb + (kc % 3) * 32768;
        const uint32_t baseB = baseA + 16384;

        #pragma unroll
        for (int ks = 0; ks < 4; ks++) {   // four k32 steps per 128-B chunk
            uint32_t a[4][4], b[2][4];
            #pragma unroll
            for (int mt = 0; mt < 4; mt++) {
                const int row = warp_m * 64 + mt * 16 + (lane & 15);
                const int chunk = ks * 2 + (lane >> 4);
                LDSM_X4(a[mt][0], a[mt][1], a[mt][2], a[mt][3],
                        baseA + row * 128 + ((chunk ^ (row & 7)) << 4));
            }
            #pragma unroll
            for (int nt = 0; nt < 2; nt++) {
                const int row = warp_n * 32 + nt * 16 + (lane & 15);
                const int chunk = ks * 2 + (lane >> 4);
                LDSM_X4(b[nt][0], b[nt][1], b[nt][2], b[nt][3],
                        baseB + row * 128 + ((chunk ^ (row & 7)) << 4));
            }
            #pragma unroll
            for (int mt = 0; mt < 4; mt++)
                #pragma unroll
                for (int nt = 0; nt < 4; nt++)
                    mma16832(acc[mt][nt], a[mt],
                             b[nt >> 1][nt & 1], b[nt >> 1][(nt & 1) + 2]);
        }
    }

    // ---- fused hinge epilogue ----
    float partial = 0.f;
    #pragma unroll
    for (int mt = 0; mt < 4; mt++) {
        const int r0 = blockIdx.y * 128 + warp_m * 64 + mt * 16 + (lane >> 2);
        const float p0 = __ldg(&g_pos[r0]) - 1.0f;   // v - pos + 1 = v - (pos-1)
        const float p1 = __ldg(&g_pos[r0 + 8]) - 1.0f;
        #pragma unroll
        for (int nt = 0; nt < 4; nt++) {
            partial += fmaxf(acc[mt][nt][0] - p0, 0.f);
            partial += fmaxf(acc[mt][nt][1] - p0, 0.f);
            partial += fmaxf(acc[mt][nt][2] - p1, 0.f);
            partial += fmaxf(acc[mt][nt][3] - p1, 0.f);
        }
    }

    #pragma unroll
    for (int o = 16; o > 0; o >>= 1)
        partial += __shfl_xor_sync(0xFFFFFFFFu, partial, o);
    __shared__ float warpsum[8];
    if (lane == 0) warpsum[wid] = partial;
    __syncthreads();
    if (tid == 0) {
        float s = 0.f;
        #pragma unroll
        for (int w = 0; w < 8; w++) s += warpsum[w];
        atomicAdd(&g_glob, (double)s);
    }
}

// ---------------------------------------------------------------------------
__global__ void finalize_kernel(float* out) {
    out[0] = (float)(g_glob - g_local / (double)L_DIM);
}

// ---------------------------------------------------------------------------
extern "C" void kernel_launch(void* const* d_in, const int* in_sizes, int n_in,
                              void* d_out, int out_size) {
    const float* q_hat  = (const float*)d_in[0];
    const float* q_real = (const float*)d_in[1];
    const float* gt     = (const float*)d_in[2];
    const float* pred   = (const float*)d_in[3];

    (void)in_sizes; (void)n_in; (void)out_size;

    prep_kernel<<<B_DIM, 256>>>(pred, gt);
    local_kernel<<<1024, 256>>>(q_hat, q_real);

    static bool attr_set = false;
    if (!attr_set) {
        cudaFuncSetAttribute(gemm_hinge_kernel,
                             cudaFuncAttributeMaxDynamicSharedMemorySize,
                             GEMM_SMEM_DYN);
        attr_set = true;
    }
    gemm_hinge_kernel<<<dim3(32, 32), 256, GEMM_SMEM_DYN>>>();

    finalize_kernel<<<1, 1>>>((float*)d_out);
}